// round 14
// baseline (speedup 1.0000x reference)
#include <cuda_runtime.h>
#include <math.h>

#define L 512
#define DS 384
#define DP 128
#define H_ 12
#define DH 32
#define QPD 144
#define VPD 288
#define PROJD 1728
#define AVD 768
#define COMBD 2304
#define EXTD 48
#define LGS 516
#define ATS 18    /* att_t row stride */
#define PTS2 136  /* pair tile row stride */
#define WPS 17    /* wpb row stride */

// ---------------- scratch ----------------
__device__ float g_sn[L*DS];
__device__ float g_proj[L*PROJD];
__device__ float g_uq[L*H_*EXTD];
__device__ float g_wk[L*H_*EXTD];
__device__ float g_avin[L*AVD];
__device__ float g_att[(size_t)H_*L*L];
__device__ float g_ptsraw[L*H_*32];
__device__ float g_comb[L*COMBD];
__device__ float g_fpart[4*L*DS];

// ---------------- tf32 helpers ----------------
__device__ __forceinline__ float tf32f(float x) {
    unsigned u;
    asm("cvt.rna.tf32.f32 %0, %1;" : "=r"(u) : "f"(x));
    return __uint_as_float(u);
}
__device__ __forceinline__ void mma_tf32(float& d0, float& d1, float& d2, float& d3,
                                         unsigned a0, unsigned a1, unsigned a2, unsigned a3,
                                         unsigned b0, unsigned b1) {
    asm("mma.sync.aligned.m16n8k8.row.col.f32.tf32.tf32.f32 "
        "{%0,%1,%2,%3}, {%4,%5,%6,%7}, {%8,%9}, {%0,%1,%2,%3};"
        : "+f"(d0), "+f"(d1), "+f"(d2), "+f"(d3)
        : "r"(a0), "r"(a1), "r"(a2), "r"(a3), "r"(b0), "r"(b1));
}
#define FB(x) __float_as_uint(x)

// ---------------- K1: LayerNorm ----------------
__global__ void k_ln(const float* __restrict__ single_, const float* __restrict__ ln_w,
                     const float* __restrict__ ln_b) {
    const int i = blockIdx.x, t = threadIdx.x;  // 384
    __shared__ float red[512];
    float x = single_[i*DS + t];
    red[t] = x;
    if (t < 128) red[384+t] = 0.f;
    __syncthreads();
    for (int s = 256; s > 0; s >>= 1) { if (t < s) red[t] += red[t+s]; __syncthreads(); }
    float mu = red[0] * (1.f/384.f);
    __syncthreads();
    float xc = x - mu;
    red[t] = xc*xc;
    if (t < 128) red[384+t] = 0.f;
    __syncthreads();
    for (int s = 256; s > 0; s >>= 1) { if (t < s) red[t] += red[t+s]; __syncthreads(); }
    float var = red[0] * (1.f/384.f);
    g_sn[i*DS + t] = xc * rsqrtf(var + 1e-5f) * ln_w[t] + ln_b[t];
}

// ---------------- helpers ----------------
__device__ __forceinline__ void seg_of(int c, const float* Wq, const float* Wk, const float* Wv,
                                       const float* Wqp, const float* Wkp, const float* Wvp,
                                       const float** W, int* w, int* lc) {
    if (c < 384)       { *W = Wq;  *w = 384; *lc = c; }
    else if (c < 768)  { *W = Wk;  *w = 384; *lc = c-384; }
    else if (c < 1152) { *W = Wv;  *w = 384; *lc = c-768; }
    else if (c < 1296) { *W = Wqp; *w = 144; *lc = c-1152; }
    else if (c < 1440) { *W = Wkp; *w = 144; *lc = c-1296; }
    else               { *W = Wvp; *w = 288; *lc = c-1440; }
}
__device__ __forceinline__ float bias_of(int c, const float* bq, const float* bk, const float* bv,
                                         const float* bqp, const float* bkp, const float* bvp) {
    if (c < 384) return bq[c];
    if (c < 768) return bk[c-384];
    if (c < 1152) return bv[c-768];
    if (c < 1296) return bqp[c-1152];
    if (c < 1440) return bkp[c-1296];
    return bvp[c-1440];
}

// ---------------- K2: projection GEMM (fp32, prefetch-pipelined) ----------------
__global__ void k_projgemm(const float* __restrict__ Wq, const float* __restrict__ bq,
                           const float* __restrict__ Wk, const float* __restrict__ bk,
                           const float* __restrict__ Wv, const float* __restrict__ bv,
                           const float* __restrict__ Wqp, const float* __restrict__ bqp,
                           const float* __restrict__ Wkp, const float* __restrict__ bkp,
                           const float* __restrict__ Wvp, const float* __restrict__ bvp) {
    const int n0 = blockIdx.x*64, m0 = blockIdx.y*64;
    const int t = threadIdx.x;
    const int tx = t & 15, ty = t >> 4;
    __shared__ float As[16][68], Bs[16][68];
    float acc[4][4] = {};

    const int lm = t >> 2, lk4 = (t & 3) * 4;
    const int bk_ = t >> 4, bn4 = (t & 15) * 4;

    const float* Wp; int ww, lc;
    seg_of(n0+bn4, Wq, Wk, Wv, Wqp, Wkp, Wvp, &Wp, &ww, &lc);

    float4 pa = *(const float4*)&g_sn[(m0+lm)*DS + lk4];
    float4 pb = *(const float4*)&Wp[(size_t)bk_*ww + lc];

    for (int it = 0; it < 24; it++) {
        As[lk4+0][lm] = pa.x; As[lk4+1][lm] = pa.y;
        As[lk4+2][lm] = pa.z; As[lk4+3][lm] = pa.w;
        *(float4*)&Bs[bk_][bn4] = pb;
        __syncthreads();
        if (it < 23) {
            int k0 = (it+1)*16;
            pa = *(const float4*)&g_sn[(m0+lm)*DS + k0 + lk4];
            pb = *(const float4*)&Wp[(size_t)(k0+bk_)*ww + lc];
        }
        #pragma unroll
        for (int k = 0; k < 16; k++) {
            float4 a = *(const float4*)&As[k][ty*4];
            float4 b = *(const float4*)&Bs[k][tx*4];
            acc[0][0]+=a.x*b.x; acc[0][1]+=a.x*b.y; acc[0][2]+=a.x*b.z; acc[0][3]+=a.x*b.w;
            acc[1][0]+=a.y*b.x; acc[1][1]+=a.y*b.y; acc[1][2]+=a.y*b.z; acc[1][3]+=a.y*b.w;
            acc[2][0]+=a.z*b.x; acc[2][1]+=a.z*b.y; acc[2][2]+=a.z*b.z; acc[2][3]+=a.z*b.w;
            acc[3][0]+=a.w*b.x; acc[3][1]+=a.w*b.y; acc[3][2]+=a.w*b.z; acc[3][3]+=a.w*b.w;
        }
        __syncthreads();
    }
    float bb[4];
    #pragma unroll
    for (int u = 0; u < 4; u++) bb[u] = bias_of(n0+tx*4+u, bq, bk, bv, bqp, bkp, bvp);
    #pragma unroll
    for (int um = 0; um < 4; um++) {
        float4 o = make_float4(acc[um][0]+bb[0], acc[um][1]+bb[1],
                               acc[um][2]+bb[2], acc[um][3]+bb[3]);
        *(float4*)&g_proj[(size_t)(m0+ty*4+um)*PROJD + n0 + tx*4] = o;
    }
}

// ---------------- K3: rotations + avin + extended vectors ----------------
__global__ void k_rot(const float* __restrict__ rot, const float* __restrict__ trans,
                      const float* __restrict__ wc, const float* __restrict__ wl,
                      const float* __restrict__ gamma) {
    const int i = blockIdx.x, t = threadIdx.x;  // 384
    __shared__ float Rm[9], Tv[3];
    __shared__ float qg_s[QPD], kg_s[QPD];
    __shared__ float sq_s[H_], sk_s[H_];
    if (t < 9) Rm[t] = rot[i*9 + t];
    if (t < 3) Tv[t] = trans[i*3 + t];
    __syncthreads();
    const float* pr = &g_proj[(size_t)i*PROJD];
    if (t < QPD) {
        int i3 = t % 3, base = t - i3;
        float q0 = pr[1152+base], q1 = pr[1152+base+1], q2 = pr[1152+base+2];
        float p0 = pr[1296+base], p1 = pr[1296+base+1], p2 = pr[1296+base+2];
        qg_s[t] = Rm[i3*3+0]*q0 + Rm[i3*3+1]*q1 + Rm[i3*3+2]*q2 + Tv[i3];
        kg_s[t] = Rm[i3*3+0]*p0 + Rm[i3*3+1]*p1 + Rm[i3*3+2]*p2 + Tv[i3];
    }
    if (t < VPD) {
        int i3 = t % 3, base = t - i3;
        float v0 = pr[1440+base], v1 = pr[1440+base+1], v2 = pr[1440+base+2];
        float vg = Rm[i3*3+0]*v0 + Rm[i3*3+1]*v1 + Rm[i3*3+2]*v2 + Tv[i3];
        int h = t / 24, r = t % 24;
        g_avin[i*AVD + 384 + h*32 + r] = vg;
    }
    if (t < 96) { int h = t/8, r = t%8; g_avin[i*AVD + 384 + h*32 + 24 + r] = 0.f; }
    g_avin[i*AVD + t] = pr[768 + t];
    __syncthreads();
    if (t < H_) {
        float sq = 0.f, sk = 0.f;
        #pragma unroll
        for (int u = 0; u < 12; u++) {
            float a = qg_s[t*12+u]; sq += a*a;
            float b = kg_s[t*12+u]; sk += b*b;
        }
        sq_s[t] = sq; sk_s[t] = sk;
    }
    __syncthreads();
    const float cseq = wc[0] * rsqrtf((float)DH);
    const float wlv = wl[0];
    for (int idx = t; idx < H_*EXTD; idx += 384) {
        int h = idx / EXTD, c = idx % EXTD;
        float cg = gamma[h] * wlv;
        float uq, wk;
        if (c < 32)      { uq = pr[h*32 + c] * cseq;      wk = pr[384 + h*32 + c]; }
        else if (c < 44) { int p = c-32; uq = qg_s[h*12+p] * cg; wk = kg_s[h*12+p]; }
        else if (c == 44){ uq = -0.5f*cg*sq_s[h];          wk = 1.f; }
        else if (c == 45){ uq = 1.f;                       wk = -0.5f*cg*sk_s[h]; }
        else             { uq = 0.f;                       wk = 0.f; }
        g_uq[(size_t)i*(H_*EXTD) + idx] = uq;
        g_wk[(size_t)i*(H_*EXTD) + idx] = wk;
    }
}

// ---------------- K4: logits GEMM (fp32, K=48 single stage) ----------------
__global__ void k_logits() {
    const int h = blockIdx.z;
    const int j0 = blockIdx.x*64, i0 = blockIdx.y*64;
    const int t = threadIdx.x;
    const int tx = t & 15, ty = t >> 4;
    __shared__ float Us[48][68], Ws[48][68];
    float acc[4][4] = {};
    const int LD = H_*EXTD;

    for (int f = t; f < 768; f += 256) {
        int m = f / 12, k4 = (f % 12) * 4;
        float4 u = *(const float4*)&g_uq[(size_t)(i0+m)*LD + h*EXTD + k4];
        Us[k4+0][m]=u.x; Us[k4+1][m]=u.y; Us[k4+2][m]=u.z; Us[k4+3][m]=u.w;
        float4 w = *(const float4*)&g_wk[(size_t)(j0+m)*LD + h*EXTD + k4];
        Ws[k4+0][m]=w.x; Ws[k4+1][m]=w.y; Ws[k4+2][m]=w.z; Ws[k4+3][m]=w.w;
    }
    __syncthreads();
    #pragma unroll
    for (int k = 0; k < 48; k++) {
        float4 a = *(const float4*)&Us[k][ty*4];
        float4 b = *(const float4*)&Ws[k][tx*4];
        acc[0][0]+=a.x*b.x; acc[0][1]+=a.x*b.y; acc[0][2]+=a.x*b.z; acc[0][3]+=a.x*b.w;
        acc[1][0]+=a.y*b.x; acc[1][1]+=a.y*b.y; acc[1][2]+=a.y*b.z; acc[1][3]+=a.y*b.w;
        acc[2][0]+=a.z*b.x; acc[2][1]+=a.z*b.y; acc[2][2]+=a.z*b.z; acc[2][3]+=a.z*b.w;
        acc[3][0]+=a.w*b.x; acc[3][1]+=a.w*b.y; acc[3][2]+=a.w*b.z; acc[3][3]+=a.w*b.w;
    }
    #pragma unroll
    for (int um = 0; um < 4; um++) {
        float4 o = make_float4(acc[um][0], acc[um][1], acc[um][2], acc[um][3]);
        *(float4*)&g_att[((size_t)h*L + (i0+ty*4+um))*L + j0 + tx*4] = o;
    }
}

// ---- K5: single-pass bias + online-softmax + pair_out (tf32, no exp recompute) ---
__global__ void __launch_bounds__(256, 2)
k_fused(const float* __restrict__ pair, const float* __restrict__ Wpb,
        const float* __restrict__ bpb, const float* __restrict__ mask) {
    extern __shared__ float sm[];
    float* lg     = sm;                 // 12*516 = 6192 (logits -> tile-local exps)
    float* wpb_s  = sm + 6192;          // 128*17 = 2176
    float* att_t  = sm + 8368;          // 64*18  = 1152
    float* ptile  = sm + 9520;          // 64*136 = 8704
    float* mask_s = sm + 18224;         // 512
    float* mrun   = sm + 18736;         // 12
    float* srun   = sm + 18748;         // 12
    float* fac    = sm + 18760;         // 16
    float* msave  = sm + 18776;         // 12*8 = 96 (per-tile max)
    float* ftile  = sm + 18872;         // 12*8 = 96 (final factors)
    __shared__ float bpb_s[H_];

    const int i = blockIdx.x;
    const int t = threadIdx.x;  // 256
    const int warp = t >> 5, lane = t & 31;

    const float4* psrc = (const float4*)(pair + (size_t)i*L*DP);
    float4 rg[8];
    #define LOAD_TILE(T) { _Pragma("unroll") for (int s = 0; s < 8; s++) { \
        int f = t + s*256; \
        rg[s] = psrc[(size_t)((T)*64 + (f >> 5))*32 + (f & 31)]; } }
    #define STORE_TILE() { _Pragma("unroll") for (int s = 0; s < 8; s++) { \
        int f = t + s*256; \
        float4 q = make_float4(tf32f(rg[s].x), tf32f(rg[s].y), tf32f(rg[s].z), tf32f(rg[s].w)); \
        *(float4*)&ptile[(f >> 5)*PTS2 + (f & 31)*4] = q; } }

    // init
    for (int idx = t; idx < 128*WPS; idx += 256) {
        int k = idx / WPS, n = idx % WPS;
        wpb_s[idx] = (n < 12) ? tf32f(Wpb[k*12 + n]) : 0.f;
    }
    if (t < H_) bpb_s[t] = bpb[t];
    for (int idx = t; idx < 512; idx += 256) mask_s[idx] = mask[idx];
    for (int idx = t; idx < 64*6; idx += 256) {
        int j = idx / 6, c = 12 + idx % 6;
        att_t[j*ATS + c] = 0.f;
    }
    if (t < H_) { mrun[t] = -1e30f; srun[t] = 0.f; }
    if (t < 16) fac[t] = 1.f;
    LOAD_TILE(0);
    __syncthreads();
    const float mi = mask[i];
    for (int idx = t; idx < H_*L; idx += 256) {
        int h = idx >> 9, j = idx & 511;
        float v = g_att[((size_t)h*L + i)*L + j] + bpb_s[h];
        lg[h*LGS + j] = (mi * mask_s[j] > 0.f) ? v : -1e9f;
    }
    __syncthreads();

    const int jc = warp & 3;
    const int nt = warp >> 2;
    const int cw = warp*16;
    const int h0 = lane >> 2, h1 = h0 + 8;
    float e0[4] = {}, e1[4] = {};

    for (int tile = 0; tile < 8; tile++) {
        STORE_TILE();
        __syncthreads();
        if (tile < 7) LOAD_TILE(tile+1);

        // --- bias mma ---
        {
            float d0=0.f, d1=0.f, d2=0.f, d3=0.f;
            const int ar = jc*16 + (lane >> 2);
            const int ac = lane & 3;
            const int bn = nt*8 + (lane >> 2);
            const int bk = lane & 3;
            #pragma unroll
            for (int ks = 0; ks < 16; ks++) {
                unsigned a0 = FB(ptile[ar*PTS2 + ks*8 + ac]);
                unsigned a1 = FB(ptile[(ar+8)*PTS2 + ks*8 + ac]);
                unsigned a2 = FB(ptile[ar*PTS2 + ks*8 + ac + 4]);
                unsigned a3 = FB(ptile[(ar+8)*PTS2 + ks*8 + ac + 4]);
                unsigned b0 = FB(wpb_s[(ks*8 + bk)*WPS + bn]);
                unsigned b1 = FB(wpb_s[(ks*8 + bk + 4)*WPS + bn]);
                mma_tf32(d0, d1, d2, d3, a0, a1, a2, a3, b0, b1);
            }
            int jj = tile*64 + jc*16 + (lane >> 2);
            int hh = nt*8 + (lane & 3)*2;
            if (hh < 12) {
                lg[hh*LGS + jj]       += d0;
                lg[(hh+1)*LGS + jj]   += d1;
                lg[hh*LGS + jj+8]     += d2;
                lg[(hh+1)*LGS + jj+8] += d3;
            }
        }
        __syncthreads();

        // --- online softmax: exp into lg (in place) + tf32 copy into att_t ---
        for (int h = warp; h < H_; h += 8) {
            float* row = &lg[h*LGS + tile*64];
            float v0 = row[lane], v1 = row[lane+32];
            float tm = fmaxf(v0, v1);
            #pragma unroll
            for (int o = 16; o; o >>= 1) tm = fmaxf(tm, __shfl_xor_sync(0xffffffffu, tm, o));
            float mo = mrun[h];
            float mn = fmaxf(mo, tm);
            float ev0 = __expf(v0 - mn), ev1 = __expf(v1 - mn);
            row[lane] = ev0; row[lane+32] = ev1;
            att_t[lane*ATS + h]      = tf32f(ev0);
            att_t[(lane+32)*ATS + h] = tf32f(ev1);
            float ts = ev0 + ev1;
            #pragma unroll
            for (int o = 16; o; o >>= 1) ts += __shfl_xor_sync(0xffffffffu, ts, o);
            if (lane == 0) {
                float f = __expf(mo - mn);
                srun[h] = srun[h]*f + ts;
                mrun[h] = mn;
                fac[h]  = f;
                msave[h*8 + tile] = mn;
            }
        }
        __syncthreads();

        // --- rescale accumulators ---
        {
            float f0 = fac[h0];
            float f1 = (h1 < 12) ? fac[h1] : 1.f;
            e0[0]*=f0; e0[1]*=f0; e0[2]*=f1; e0[3]*=f1;
            e1[0]*=f0; e1[1]*=f0; e1[2]*=f1; e1[3]*=f1;
        }

        // --- pair_out mma over this tile ---
        #pragma unroll
        for (int ks = 0; ks < 8; ks++) {
            unsigned a0 = FB(att_t[(ks*8 + (lane & 3))*ATS + (lane >> 2)]);
            unsigned a1 = FB(att_t[(ks*8 + (lane & 3))*ATS + (lane >> 2) + 8]);
            unsigned a2 = FB(att_t[(ks*8 + (lane & 3) + 4)*ATS + (lane >> 2)]);
            unsigned a3 = FB(att_t[(ks*8 + (lane & 3) + 4)*ATS + (lane >> 2) + 8]);
            unsigned b0 = FB(ptile[(ks*8 + (lane & 3))*PTS2 + cw + (lane >> 2)]);
            unsigned b1 = FB(ptile[(ks*8 + (lane & 3) + 4)*PTS2 + cw + (lane >> 2)]);
            mma_tf32(e0[0], e0[1], e0[2], e0[3], a0, a1, a2, a3, b0, b1);
            unsigned c0 = FB(ptile[(ks*8 + (lane & 3))*PTS2 + cw + 8 + (lane >> 2)]);
            unsigned c1 = FB(ptile[(ks*8 + (lane & 3) + 4)*PTS2 + cw + 8 + (lane >> 2)]);
            mma_tf32(e1[0], e1[1], e1[2], e1[3], a0, a1, a2, a3, c0, c1);
        }
        __syncthreads();
    }

    // --- final factors: 96 exps total, then attn = lg * ftile ---
    if (t < 96) {
        int h = t >> 3;
        ftile[t] = __expf(msave[t] - mrun[h]) / srun[h];
    }
    __syncthreads();
    for (int h = warp; h < H_; h += 8) {
        const float* row = &lg[h*LGS];
        const float* ft = &ftile[h*8];
        for (int j = lane; j < L; j += 32)
            g_att[((size_t)h*L + i)*L + j] = row[j] * ft[j >> 6];
    }

    // --- pair_out store ---
    {
        int c0 = cw + (lane & 3)*2;
        float* dst = &g_comb[(size_t)i*COMBD + 768];
        float is0 = 1.f / srun[h0];
        dst[h0*DP + c0]         = e0[0]*is0;
        dst[h0*DP + c0 + 1]     = e0[1]*is0;
        dst[h0*DP + c0 + 8]     = e1[0]*is0;
        dst[h0*DP + c0 + 8 + 1] = e1[1]*is0;
        if (h1 < 12) {
            float is1 = 1.f / srun[h1];
            dst[h1*DP + c0]         = e0[2]*is1;
            dst[h1*DP + c0 + 1]     = e0[3]*is1;
            dst[h1*DP + c0 + 8]     = e1[2]*is1;
            dst[h1*DP + c0 + 8 + 1] = e1[3]*is1;
        }
    }
    #undef LOAD_TILE
    #undef STORE_TILE
}

// ---------------- K6: attn @ [v|vg] per head (tf32, pipelined) ----------------
__global__ void k_av() {
    const int h = blockIdx.x;
    const int m0 = blockIdx.y*64;
    const int t = threadIdx.x;  // 256
    const int warp = t >> 5, lane = t & 31;
    __shared__ float As[64][68];
    __shared__ float Bs[64][68];

    const int wm = warp & 3;
    const int wn = warp >> 2;
    float acc[4][4] = {};
    float4 ra[4], rb[4];

    const int lr = t >> 4, lc4 = (t & 15) * 4;
    const int bcol = (lc4 < 32) ? (h*32 + lc4) : (384 + h*32 + lc4 - 32);

    #define AV_LOAD(KC) { _Pragma("unroll") for (int s = 0; s < 4; s++) { \
        int r = lr + s*16; \
        ra[s] = *(const float4*)&g_att[((size_t)h*L + m0 + r)*L + (KC)*64 + lc4]; \
        rb[s] = *(const float4*)&g_avin[((KC)*64 + r)*AVD + bcol]; } }
    #define AV_STORE() { _Pragma("unroll") for (int s = 0; s < 4; s++) { \
        int r = lr + s*16; \
        *(float4*)&As[r][lc4] = make_float4(tf32f(ra[s].x), tf32f(ra[s].y), tf32f(ra[s].z), tf32f(ra[s].w)); \
        *(float4*)&Bs[r][lc4] = make_float4(tf32f(rb[s].x), tf32f(rb[s].y), tf32f(rb[s].z), tf32f(rb[s].w)); } }

    AV_LOAD(0);
    for (int kc = 0; kc < 8; kc++) {
        AV_STORE();
        __syncthreads();
        if (kc < 7) AV_LOAD(kc+1);
        const int ar = wm*16 + (lane >> 2);
        const int ac = lane & 3;
        #pragma unroll
        for (int ks = 0; ks < 8; ks++) {
            unsigned a0 = FB(As[ar][ks*8 + ac]);
            unsigned a1 = FB(As[ar+8][ks*8 + ac]);
            unsigned a2 = FB(As[ar][ks*8 + ac + 4]);
            unsigned a3 = FB(As[ar+8][ks*8 + ac + 4]);
            #pragma unroll
            for (int ns = 0; ns < 4; ns++) {
                int bn = wn*32 + ns*8 + (lane >> 2);
                unsigned b0 = FB(Bs[ks*8 + (lane & 3)][bn]);
                unsigned b1 = FB(Bs[ks*8 + (lane & 3) + 4][bn]);
                mma_tf32(acc[ns][0], acc[ns][1], acc[ns][2], acc[ns][3],
                         a0, a1, a2, a3, b0, b1);
            }
        }
        __syncthreads();
    }
    #undef AV_LOAD
    #undef AV_STORE
    {
        int r0 = m0 + wm*16 + (lane >> 2);
        int r1 = r0 + 8;
        #pragma unroll
        for (int ns = 0; ns < 4; ns++) {
            int col = wn*32 + ns*8 + (lane & 3)*2;
            if (col < 32) {
                g_comb[(size_t)r0*COMBD + h*32 + col]     = acc[ns][0];
                g_comb[(size_t)r0*COMBD + h*32 + col + 1] = acc[ns][1];
                g_comb[(size_t)r1*COMBD + h*32 + col]     = acc[ns][2];
                g_comb[(size_t)r1*COMBD + h*32 + col + 1] = acc[ns][3];
            } else {
                int c2 = col - 32;
                g_ptsraw[r0*384 + h*32 + c2]     = acc[ns][0];
                g_ptsraw[r0*384 + h*32 + c2 + 1] = acc[ns][1];
                g_ptsraw[r1*384 + h*32 + c2]     = acc[ns][2];
                g_ptsraw[r1*384 + h*32 + c2 + 1] = acc[ns][3];
            }
        }
    }
}

// ---------------- K7: point frame transform + norm ----------------
__global__ void k_pts(const float* __restrict__ rot, const float* __restrict__ trans) {
    int idx = blockIdx.x*256 + threadIdx.x;
    if (idx >= L*96) return;
    int i = idx / 96, u = idx % 96;
    int h = u >> 3, p = u & 7;
    const float* src = &g_ptsraw[i*384 + h*32 + p*3];
    float T0 = trans[i*3+0], T1 = trans[i*3+1], T2 = trans[i*3+2];
    float px = src[0]-T0, py = src[1]-T1, pz = src[2]-T2;
    const float* R = &rot[i*9];
    float lx = R[0]*px + R[3]*py + R[6]*pz;
    float ly = R[1]*px + R[4]*py + R[7]*pz;
    float lz = R[2]*px + R[5]*py + R[8]*pz;
    float nrm = sqrtf(lx*lx + ly*ly + lz*lz);
    float* dst = &g_comb[(size_t)i*COMBD + 384 + u*4];
    dst[0] = nrm; dst[1] = lx; dst[2] = ly; dst[3] = lz;
}

// ---------------- K8: combined @ Wo, split-K=4 (tf32, pipelined) ----------------
__global__ void k_final4(const float* __restrict__ Wo) {
    const int kc4 = blockIdx.z;
    const int n0 = blockIdx.x*64, m0 = blockIdx.y*64;
    const int t = threadIdx.x;  // 256
    const int warp = t >> 5, lane = t & 31;
    __shared__ float As[64][68];
    __shared__ float Bs[64][68];

    const int wm = warp & 3;
    const int wn = warp >> 2;
    float acc[4][4] = {};
    float4 ra[4], rb[4];

    const int lr = t >> 4, lc4 = (t & 15) * 4;
    const int kbeg = kc4*576;

    #define F4_LOAD(KC) { int k0 = kbeg + (KC)*64; _Pragma("unroll") for (int s = 0; s < 4; s++) { \
        int r = lr + s*16; \
        ra[s] = *(const float4*)&g_comb[(size_t)(m0 + r)*COMBD + k0 + lc4]; \
        rb[s] = *(const float4*)&Wo[(size_t)(k0 + r)*DS + n0 + lc4]; } }
    #define F4_STORE() { _Pragma("unroll") for (int s = 0; s < 4; s++) { \
        int r = lr + s*16; \
        *(float4*)&As[r][lc4] = make_float4(tf32f(ra[s].x), tf32f(ra[s].y), tf32f(ra[s].z), tf32f(ra[s].w)); \
        *(float4*)&Bs[r][lc4] = make_float4(tf32f(rb[s].x), tf32f(rb[s].y), tf32f(rb[s].z), tf32f(rb[s].w)); } }

    F4_LOAD(0);
    for (int kc = 0; kc < 9; kc++) {
        F4_STORE();
        __syncthreads();
        if (kc < 8) F4_LOAD(kc+1);
        const int ar = wm*16 + (lane >> 2);
        const int ac = lane & 3;
        #pragma unroll
        for (int ks = 0; ks < 8; ks++) {
            unsigned a0 = FB(As[ar][ks*8 + ac]);
            unsigned a1 = FB(As[ar+8][ks*8 + ac]);
            unsigned a2 = FB(As[ar][ks*8 + ac + 4]);
            unsigned a3 = FB(As[ar+8][ks*8 + ac + 4]);
            #pragma unroll
            for (int ns = 0; ns < 4; ns++) {
                int bn = wn*32 + ns*8 + (lane >> 2);
                unsigned b0 = FB(Bs[ks*8 + (lane & 3)][bn]);
                unsigned b1 = FB(Bs[ks*8 + (lane & 3) + 4][bn]);
                mma_tf32(acc[ns][0], acc[ns][1], acc[ns][2], acc[ns][3],
                         a0, a1, a2, a3, b0, b1);
            }
        }
        __syncthreads();
    }
    #undef F4_LOAD
    #undef F4_STORE
    {
        int r0 = m0 + wm*16 + (lane >> 2);
        int r1 = r0 + 8;
        #pragma unroll
        for (int ns = 0; ns < 4; ns++) {
            int col = n0 + wn*32 + ns*8 + (lane & 3)*2;
            g_fpart[((size_t)kc4*L + r0)*DS + col]     = acc[ns][0];
            g_fpart[((size_t)kc4*L + r0)*DS + col + 1] = acc[ns][1];
            g_fpart[((size_t)kc4*L + r1)*DS + col]     = acc[ns][2];
            g_fpart[((size_t)kc4*L + r1)*DS + col + 1] = acc[ns][3];
        }
    }
}

__global__ void k_fred(const float* __restrict__ bo, float* __restrict__ out) {
    int f = blockIdx.x*256 + threadIdx.x;
    int n = (f*4) % DS;
    float4 p0 = *(const float4*)&g_fpart[(size_t)0*L*DS + f*4];
    float4 p1 = *(const float4*)&g_fpart[(size_t)1*L*DS + f*4];
    float4 p2 = *(const float4*)&g_fpart[(size_t)2*L*DS + f*4];
    float4 p3 = *(const float4*)&g_fpart[(size_t)3*L*DS + f*4];
    float4 bb = *(const float4*)&bo[n];
    float4 o = make_float4(p0.x+p1.x+p2.x+p3.x+bb.x, p0.y+p1.y+p2.y+p3.y+bb.y,
                           p0.z+p1.z+p2.z+p3.z+bb.z, p0.w+p1.w+p2.w+p3.w+bb.w);
    *(float4*)&out[f*4] = o;
}

// ---------------- launch ----------------
extern "C" void kernel_launch(void* const* d_in, const int* in_sizes, int n_in,
                              void* d_out, int out_size) {
    const float* single_ = (const float*)d_in[0];
    const float* pair    = (const float*)d_in[1];
    const float* rot     = (const float*)d_in[2];
    const float* trans   = (const float*)d_in[3];
    const float* mask    = (const float*)d_in[4];
    const float* ln_w    = (const float*)d_in[5];
    const float* ln_b    = (const float*)d_in[6];
    const float* Wq      = (const float*)d_in[7];
    const float* bq      = (const float*)d_in[8];
    const float* Wk      = (const float*)d_in[9];
    const float* bk      = (const float*)d_in[10];
    const float* Wv      = (const float*)d_in[11];
    const float* bv      = (const float*)d_in[12];
    const float* Wqp     = (const float*)d_in[13];
    const float* bqp     = (const float*)d_in[14];
    const float* Wkp     = (const float*)d_in[15];
    const float* bkp     = (const float*)d_in[16];
    const float* Wvp     = (const float*)d_in[17];
    const float* bvp     = (const float*)d_in[18];
    const float* Wpb     = (const float*)d_in[19];
    const float* bpb     = (const float*)d_in[20];
    const float* Wo      = (const float*)d_in[21];
    const float* bo      = (const float*)d_in[22];
    const float* w_c     = (const float*)d_in[23];
    const float* w_l     = (const float*)d_in[24];
    const float* gamma_h = (const float*)d_in[25];

    k_ln<<<L, 384>>>(single_, ln_w, ln_b);
    k_projgemm<<<dim3(PROJD/64, L/64), 256>>>(Wq, bq, Wk, bk, Wv, bv,
                                              Wqp, bqp, Wkp, bkp, Wvp, bvp);
    k_rot<<<L, 384>>>(rot, trans, w_c, w_l, gamma_h);
    k_logits<<<dim3(L/64, L/64, H_), 256>>>();

    const int dyn = 18968 * (int)sizeof(float);  // 75872
    cudaFuncSetAttribute(k_fused, cudaFuncAttributeMaxDynamicSharedMemorySize, dyn);
    k_fused<<<L, 256, dyn>>>(pair, Wpb, bpb, mask);

    k_av<<<dim3(H_, L/64), 256>>>();
    k_pts<<<(L*96 + 255)/256, 256>>>(rot, trans);
    k_final4<<<dim3(DS/64, L/64, 4), 256>>>(Wo);
    k_fred<<<192, 256>>>(bo, (float*)d_out);
}

// round 15
// speedup vs baseline: 1.0655x; 1.0655x over previous
#include <cuda_runtime.h>
#include <math.h>

#define L 512
#define DS 384
#define DP 128
#define H_ 12
#define DH 32
#define QPD 144
#define VPD 288
#define PROJD 1728
#define AVD 768
#define COMBD 2304
#define EXTD 48
#define LGS 516
#define ATS 18    /* att_t row stride */
#define PTS2 136  /* pair tile row stride */
#define WPS 17    /* wpb row stride */

// ---------------- scratch ----------------
__device__ float g_sn[L*DS];
__device__ float g_proj[L*PROJD];
__device__ float g_uq[L*H_*EXTD];
__device__ float g_wk[L*H_*EXTD];
__device__ float g_avin[L*AVD];
__device__ float g_att[(size_t)H_*L*L];
__device__ float g_ptsraw[L*H_*32];
__device__ float g_comb[L*COMBD];
__device__ float g_fpart[6*L*DS];

// ---------------- tf32 helpers ----------------
__device__ __forceinline__ float tf32f(float x) {
    unsigned u;
    asm("cvt.rna.tf32.f32 %0, %1;" : "=r"(u) : "f"(x));
    return __uint_as_float(u);
}
__device__ __forceinline__ void mma_tf32(float& d0, float& d1, float& d2, float& d3,
                                         unsigned a0, unsigned a1, unsigned a2, unsigned a3,
                                         unsigned b0, unsigned b1) {
    asm("mma.sync.aligned.m16n8k8.row.col.f32.tf32.tf32.f32 "
        "{%0,%1,%2,%3}, {%4,%5,%6,%7}, {%8,%9}, {%0,%1,%2,%3};"
        : "+f"(d0), "+f"(d1), "+f"(d2), "+f"(d3)
        : "r"(a0), "r"(a1), "r"(a2), "r"(a3), "r"(b0), "r"(b1));
}
#define FB(x) __float_as_uint(x)

// ---------------- K1: LayerNorm ----------------
__global__ void k_ln(const float* __restrict__ single_, const float* __restrict__ ln_w,
                     const float* __restrict__ ln_b) {
    const int i = blockIdx.x, t = threadIdx.x;  // 384
    __shared__ float red[512];
    float x = single_[i*DS + t];
    red[t] = x;
    if (t < 128) red[384+t] = 0.f;
    __syncthreads();
    for (int s = 256; s > 0; s >>= 1) { if (t < s) red[t] += red[t+s]; __syncthreads(); }
    float mu = red[0] * (1.f/384.f);
    __syncthreads();
    float xc = x - mu;
    red[t] = xc*xc;
    if (t < 128) red[384+t] = 0.f;
    __syncthreads();
    for (int s = 256; s > 0; s >>= 1) { if (t < s) red[t] += red[t+s]; __syncthreads(); }
    float var = red[0] * (1.f/384.f);
    g_sn[i*DS + t] = xc * rsqrtf(var + 1e-5f) * ln_w[t] + ln_b[t];
}

// ---------------- helpers ----------------
__device__ __forceinline__ void seg_of(int c, const float* Wq, const float* Wk, const float* Wv,
                                       const float* Wqp, const float* Wkp, const float* Wvp,
                                       const float** W, int* w, int* lc) {
    if (c < 384)       { *W = Wq;  *w = 384; *lc = c; }
    else if (c < 768)  { *W = Wk;  *w = 384; *lc = c-384; }
    else if (c < 1152) { *W = Wv;  *w = 384; *lc = c-768; }
    else if (c < 1296) { *W = Wqp; *w = 144; *lc = c-1152; }
    else if (c < 1440) { *W = Wkp; *w = 144; *lc = c-1296; }
    else               { *W = Wvp; *w = 288; *lc = c-1440; }
}
__device__ __forceinline__ float bias_of(int c, const float* bq, const float* bk, const float* bv,
                                         const float* bqp, const float* bkp, const float* bvp) {
    if (c < 384) return bq[c];
    if (c < 768) return bk[c-384];
    if (c < 1152) return bv[c-768];
    if (c < 1296) return bqp[c-1152];
    if (c < 1440) return bkp[c-1296];
    return bvp[c-1440];
}

// ---------------- K2: projection GEMM (fp32, prefetch-pipelined) ----------------
__global__ void k_projgemm(const float* __restrict__ Wq, const float* __restrict__ bq,
                           const float* __restrict__ Wk, const float* __restrict__ bk,
                           const float* __restrict__ Wv, const float* __restrict__ bv,
                           const float* __restrict__ Wqp, const float* __restrict__ bqp,
                           const float* __restrict__ Wkp, const float* __restrict__ bkp,
                           const float* __restrict__ Wvp, const float* __restrict__ bvp) {
    const int n0 = blockIdx.x*64, m0 = blockIdx.y*64;
    const int t = threadIdx.x;
    const int tx = t & 15, ty = t >> 4;
    __shared__ float As[16][68], Bs[16][68];
    float acc[4][4] = {};

    const int lm = t >> 2, lk4 = (t & 3) * 4;
    const int bk_ = t >> 4, bn4 = (t & 15) * 4;

    const float* Wp; int ww, lc;
    seg_of(n0+bn4, Wq, Wk, Wv, Wqp, Wkp, Wvp, &Wp, &ww, &lc);

    float4 pa = *(const float4*)&g_sn[(m0+lm)*DS + lk4];
    float4 pb = *(const float4*)&Wp[(size_t)bk_*ww + lc];

    for (int it = 0; it < 24; it++) {
        As[lk4+0][lm] = pa.x; As[lk4+1][lm] = pa.y;
        As[lk4+2][lm] = pa.z; As[lk4+3][lm] = pa.w;
        *(float4*)&Bs[bk_][bn4] = pb;
        __syncthreads();
        if (it < 23) {
            int k0 = (it+1)*16;
            pa = *(const float4*)&g_sn[(m0+lm)*DS + k0 + lk4];
            pb = *(const float4*)&Wp[(size_t)(k0+bk_)*ww + lc];
        }
        #pragma unroll
        for (int k = 0; k < 16; k++) {
            float4 a = *(const float4*)&As[k][ty*4];
            float4 b = *(const float4*)&Bs[k][tx*4];
            acc[0][0]+=a.x*b.x; acc[0][1]+=a.x*b.y; acc[0][2]+=a.x*b.z; acc[0][3]+=a.x*b.w;
            acc[1][0]+=a.y*b.x; acc[1][1]+=a.y*b.y; acc[1][2]+=a.y*b.z; acc[1][3]+=a.y*b.w;
            acc[2][0]+=a.z*b.x; acc[2][1]+=a.z*b.y; acc[2][2]+=a.z*b.z; acc[2][3]+=a.z*b.w;
            acc[3][0]+=a.w*b.x; acc[3][1]+=a.w*b.y; acc[3][2]+=a.w*b.z; acc[3][3]+=a.w*b.w;
        }
        __syncthreads();
    }
    float bb[4];
    #pragma unroll
    for (int u = 0; u < 4; u++) bb[u] = bias_of(n0+tx*4+u, bq, bk, bv, bqp, bkp, bvp);
    #pragma unroll
    for (int um = 0; um < 4; um++) {
        float4 o = make_float4(acc[um][0]+bb[0], acc[um][1]+bb[1],
                               acc[um][2]+bb[2], acc[um][3]+bb[3]);
        *(float4*)&g_proj[(size_t)(m0+ty*4+um)*PROJD + n0 + tx*4] = o;
    }
}

// ---------------- K3: rotations + avin + extended vectors ----------------
__global__ void k_rot(const float* __restrict__ rot, const float* __restrict__ trans,
                      const float* __restrict__ wc, const float* __restrict__ wl,
                      const float* __restrict__ gamma) {
    const int i = blockIdx.x, t = threadIdx.x;  // 384
    __shared__ float Rm[9], Tv[3];
    __shared__ float qg_s[QPD], kg_s[QPD];
    __shared__ float sq_s[H_], sk_s[H_];
    if (t < 9) Rm[t] = rot[i*9 + t];
    if (t < 3) Tv[t] = trans[i*3 + t];
    __syncthreads();
    const float* pr = &g_proj[(size_t)i*PROJD];
    if (t < QPD) {
        int i3 = t % 3, base = t - i3;
        float q0 = pr[1152+base], q1 = pr[1152+base+1], q2 = pr[1152+base+2];
        float p0 = pr[1296+base], p1 = pr[1296+base+1], p2 = pr[1296+base+2];
        qg_s[t] = Rm[i3*3+0]*q0 + Rm[i3*3+1]*q1 + Rm[i3*3+2]*q2 + Tv[i3];
        kg_s[t] = Rm[i3*3+0]*p0 + Rm[i3*3+1]*p1 + Rm[i3*3+2]*p2 + Tv[i3];
    }
    if (t < VPD) {
        int i3 = t % 3, base = t - i3;
        float v0 = pr[1440+base], v1 = pr[1440+base+1], v2 = pr[1440+base+2];
        float vg = Rm[i3*3+0]*v0 + Rm[i3*3+1]*v1 + Rm[i3*3+2]*v2 + Tv[i3];
        int h = t / 24, r = t % 24;
        g_avin[i*AVD + 384 + h*32 + r] = vg;
    }
    if (t < 96) { int h = t/8, r = t%8; g_avin[i*AVD + 384 + h*32 + 24 + r] = 0.f; }
    g_avin[i*AVD + t] = pr[768 + t];
    __syncthreads();
    if (t < H_) {
        float sq = 0.f, sk = 0.f;
        #pragma unroll
        for (int u = 0; u < 12; u++) {
            float a = qg_s[t*12+u]; sq += a*a;
            float b = kg_s[t*12+u]; sk += b*b;
        }
        sq_s[t] = sq; sk_s[t] = sk;
    }
    __syncthreads();
    const float cseq = wc[0] * rsqrtf((float)DH);
    const float wlv = wl[0];
    for (int idx = t; idx < H_*EXTD; idx += 384) {
        int h = idx / EXTD, c = idx % EXTD;
        float cg = gamma[h] * wlv;
        float uq, wk;
        if (c < 32)      { uq = pr[h*32 + c] * cseq;      wk = pr[384 + h*32 + c]; }
        else if (c < 44) { int p = c-32; uq = qg_s[h*12+p] * cg; wk = kg_s[h*12+p]; }
        else if (c == 44){ uq = -0.5f*cg*sq_s[h];          wk = 1.f; }
        else if (c == 45){ uq = 1.f;                       wk = -0.5f*cg*sk_s[h]; }
        else             { uq = 0.f;                       wk = 0.f; }
        g_uq[(size_t)i*(H_*EXTD) + idx] = uq;
        g_wk[(size_t)i*(H_*EXTD) + idx] = wk;
    }
}

// ---------------- K4: logits GEMM (fp32, K=48 single stage) ----------------
__global__ void k_logits() {
    const int h = blockIdx.z;
    const int j0 = blockIdx.x*64, i0 = blockIdx.y*64;
    const int t = threadIdx.x;
    const int tx = t & 15, ty = t >> 4;
    __shared__ float Us[48][68], Ws[48][68];
    float acc[4][4] = {};
    const int LD = H_*EXTD;

    for (int f = t; f < 768; f += 256) {
        int m = f / 12, k4 = (f % 12) * 4;
        float4 u = *(const float4*)&g_uq[(size_t)(i0+m)*LD + h*EXTD + k4];
        Us[k4+0][m]=u.x; Us[k4+1][m]=u.y; Us[k4+2][m]=u.z; Us[k4+3][m]=u.w;
        float4 w = *(const float4*)&g_wk[(size_t)(j0+m)*LD + h*EXTD + k4];
        Ws[k4+0][m]=w.x; Ws[k4+1][m]=w.y; Ws[k4+2][m]=w.z; Ws[k4+3][m]=w.w;
    }
    __syncthreads();
    #pragma unroll
    for (int k = 0; k < 48; k++) {
        float4 a = *(const float4*)&Us[k][ty*4];
        float4 b = *(const float4*)&Ws[k][tx*4];
        acc[0][0]+=a.x*b.x; acc[0][1]+=a.x*b.y; acc[0][2]+=a.x*b.z; acc[0][3]+=a.x*b.w;
        acc[1][0]+=a.y*b.x; acc[1][1]+=a.y*b.y; acc[1][2]+=a.y*b.z; acc[1][3]+=a.y*b.w;
        acc[2][0]+=a.z*b.x; acc[2][1]+=a.z*b.y; acc[2][2]+=a.z*b.z; acc[2][3]+=a.z*b.w;
        acc[3][0]+=a.w*b.x; acc[3][1]+=a.w*b.y; acc[3][2]+=a.w*b.z; acc[3][3]+=a.w*b.w;
    }
    #pragma unroll
    for (int um = 0; um < 4; um++) {
        float4 o = make_float4(acc[um][0], acc[um][1], acc[um][2], acc[um][3]);
        *(float4*)&g_att[((size_t)h*L + (i0+ty*4+um))*L + j0 + tx*4] = o;
    }
}

// ---- K5: single-pass bias + online-softmax + pair_out (tf32, truncated staging) ---
__global__ void __launch_bounds__(256, 2)
k_fused(const float* __restrict__ pair, const float* __restrict__ Wpb,
        const float* __restrict__ bpb, const float* __restrict__ mask) {
    extern __shared__ float sm[];
    float* lg     = sm;                 // 12*516 = 6192
    float* wpb_s  = sm + 6192;          // 128*17 = 2176
    float* att_t  = sm + 8368;          // 64*18  = 1152
    float* ptile  = sm + 9520;          // 64*136 = 8704
    float* mask_s = sm + 18224;         // 512
    float* mrun   = sm + 18736;         // 12
    float* srun   = sm + 18748;         // 12
    float* fac    = sm + 18760;         // 16
    float* msave  = sm + 18776;         // 96
    float* ftile  = sm + 18872;         // 96
    __shared__ float bpb_s[H_];

    const int i = blockIdx.x;
    const int t = threadIdx.x;  // 256
    const int warp = t >> 5, lane = t & 31;

    const float4* psrc = (const float4*)(pair + (size_t)i*L*DP);
    float4 rg[8];
    #define LOAD_TILE(T) { _Pragma("unroll") for (int s = 0; s < 8; s++) { \
        int f = t + s*256; \
        rg[s] = psrc[(size_t)((T)*64 + (f >> 5))*32 + (f & 31)]; } }
    // truncated tf32 staging: mma reads top bits of raw fp32
    #define STORE_TILE() { _Pragma("unroll") for (int s = 0; s < 8; s++) { \
        int f = t + s*256; \
        *(float4*)&ptile[(f >> 5)*PTS2 + (f & 31)*4] = rg[s]; } }

    for (int idx = t; idx < 128*WPS; idx += 256) {
        int k = idx / WPS, n = idx % WPS;
        wpb_s[idx] = (n < 12) ? tf32f(Wpb[k*12 + n]) : 0.f;
    }
    if (t < H_) bpb_s[t] = bpb[t];
    for (int idx = t; idx < 512; idx += 256) mask_s[idx] = mask[idx];
    for (int idx = t; idx < 64*6; idx += 256) {
        int j = idx / 6, c = 12 + idx % 6;
        att_t[j*ATS + c] = 0.f;
    }
    if (t < H_) { mrun[t] = -1e30f; srun[t] = 0.f; }
    if (t < 16) fac[t] = 1.f;
    LOAD_TILE(0);
    __syncthreads();
    const float mi = mask[i];
    for (int idx = t; idx < H_*L; idx += 256) {
        int h = idx >> 9, j = idx & 511;
        float v = g_att[((size_t)h*L + i)*L + j] + bpb_s[h];
        lg[h*LGS + j] = (mi * mask_s[j] > 0.f) ? v : -1e9f;
    }
    __syncthreads();

    const int jc = warp & 3;
    const int nt = warp >> 2;
    const int cw = warp*16;
    const int h0 = lane >> 2, h1 = h0 + 8;
    float e0[4] = {}, e1[4] = {};

    for (int tile = 0; tile < 8; tile++) {
        STORE_TILE();
        __syncthreads();
        if (tile < 7) LOAD_TILE(tile+1);

        // --- bias mma ---
        {
            float d0=0.f, d1=0.f, d2=0.f, d3=0.f;
            const int ar = jc*16 + (lane >> 2);
            const int ac = lane & 3;
            const int bn = nt*8 + (lane >> 2);
            const int bk = lane & 3;
            #pragma unroll
            for (int ks = 0; ks < 16; ks++) {
                unsigned a0 = FB(ptile[ar*PTS2 + ks*8 + ac]);
                unsigned a1 = FB(ptile[(ar+8)*PTS2 + ks*8 + ac]);
                unsigned a2 = FB(ptile[ar*PTS2 + ks*8 + ac + 4]);
                unsigned a3 = FB(ptile[(ar+8)*PTS2 + ks*8 + ac + 4]);
                unsigned b0 = FB(wpb_s[(ks*8 + bk)*WPS + bn]);
                unsigned b1 = FB(wpb_s[(ks*8 + bk + 4)*WPS + bn]);
                mma_tf32(d0, d1, d2, d3, a0, a1, a2, a3, b0, b1);
            }
            int jj = tile*64 + jc*16 + (lane >> 2);
            int hh = nt*8 + (lane & 3)*2;
            if (hh < 12) {
                lg[hh*LGS + jj]       += d0;
                lg[(hh+1)*LGS + jj]   += d1;
                lg[hh*LGS + jj+8]     += d2;
                lg[(hh+1)*LGS + jj+8] += d3;
            }
        }
        __syncthreads();

        // --- online softmax ---
        for (int h = warp; h < H_; h += 8) {
            float* row = &lg[h*LGS + tile*64];
            float v0 = row[lane], v1 = row[lane+32];
            float tm = fmaxf(v0, v1);
            #pragma unroll
            for (int o = 16; o; o >>= 1) tm = fmaxf(tm, __shfl_xor_sync(0xffffffffu, tm, o));
            float mo = mrun[h];
            float mn = fmaxf(mo, tm);
            float ev0 = __expf(v0 - mn), ev1 = __expf(v1 - mn);
            row[lane] = ev0; row[lane+32] = ev1;
            att_t[lane*ATS + h]      = tf32f(ev0);
            att_t[(lane+32)*ATS + h] = tf32f(ev1);
            float ts = ev0 + ev1;
            #pragma unroll
            for (int o = 16; o; o >>= 1) ts += __shfl_xor_sync(0xffffffffu, ts, o);
            if (lane == 0) {
                float f = __expf(mo - mn);
                srun[h] = srun[h]*f + ts;
                mrun[h] = mn;
                fac[h]  = f;
                msave[h*8 + tile] = mn;
            }
        }
        __syncthreads();

        // --- rescale accumulators ---
        {
            float f0 = fac[h0];
            float f1 = (h1 < 12) ? fac[h1] : 1.f;
            e0[0]*=f0; e0[1]*=f0; e0[2]*=f1; e0[3]*=f1;
            e1[0]*=f0; e1[1]*=f0; e1[2]*=f1; e1[3]*=f1;
        }

        // --- pair_out mma ---
        #pragma unroll
        for (int ks = 0; ks < 8; ks++) {
            unsigned a0 = FB(att_t[(ks*8 + (lane & 3))*ATS + (lane >> 2)]);
            unsigned a1 = FB(att_t[(ks*8 + (lane & 3))*ATS + (lane >> 2) + 8]);
            unsigned a2 = FB(att_t[(ks*8 + (lane & 3) + 4)*ATS + (lane >> 2)]);
            unsigned a3 = FB(att_t[(ks*8 + (lane & 3) + 4)*ATS + (lane >> 2) + 8]);
            unsigned b0 = FB(ptile[(ks*8 + (lane & 3))*PTS2 + cw + (lane >> 2)]);
            unsigned b1 = FB(ptile[(ks*8 + (lane & 3) + 4)*PTS2 + cw + (lane >> 2)]);
            mma_tf32(e0[0], e0[1], e0[2], e0[3], a0, a1, a2, a3, b0, b1);
            unsigned c0 = FB(ptile[(ks*8 + (lane & 3))*PTS2 + cw + 8 + (lane >> 2)]);
            unsigned c1 = FB(ptile[(ks*8 + (lane & 3) + 4)*PTS2 + cw + 8 + (lane >> 2)]);
            mma_tf32(e1[0], e1[1], e1[2], e1[3], a0, a1, a2, a3, c0, c1);
        }
        __syncthreads();
    }

    if (t < 96) {
        int h = t >> 3;
        ftile[t] = __expf(msave[t] - mrun[h]) / srun[h];
    }
    __syncthreads();
    for (int h = warp; h < H_; h += 8) {
        const float* row = &lg[h*LGS];
        const float* ft = &ftile[h*8];
        for (int j = lane; j < L; j += 32)
            g_att[((size_t)h*L + i)*L + j] = row[j] * ft[j >> 6];
    }

    {
        int c0 = cw + (lane & 3)*2;
        float* dst = &g_comb[(size_t)i*COMBD + 768];
        float is0 = 1.f / srun[h0];
        dst[h0*DP + c0]         = e0[0]*is0;
        dst[h0*DP + c0 + 1]     = e0[1]*is0;
        dst[h0*DP + c0 + 8]     = e1[0]*is0;
        dst[h0*DP + c0 + 8 + 1] = e1[1]*is0;
        if (h1 < 12) {
            float is1 = 1.f / srun[h1];
            dst[h1*DP + c0]         = e0[2]*is1;
            dst[h1*DP + c0 + 1]     = e0[3]*is1;
            dst[h1*DP + c0 + 8]     = e1[2]*is1;
            dst[h1*DP + c0 + 8 + 1] = e1[3]*is1;
        }
    }
    #undef LOAD_TILE
    #undef STORE_TILE
}

// ---------------- K6: attn @ [v|vg] per head (tf32, 32-row tiles) ----------------
__global__ void k_av() {
    const int h = blockIdx.x;
    const int m0 = blockIdx.y*32;
    const int t = threadIdx.x;  // 256
    const int warp = t >> 5, lane = t & 31;
    __shared__ float As[32][68];
    __shared__ float Bs[64][68];

    const int wm = warp & 1;      // 2 m-chunks of 16
    const int wn = warp >> 1;     // 4 n-chunks of 16
    float acc[2][4] = {};
    float4 ra[2], rb[4];

    const int alr = t >> 4, lc4 = (t & 15) * 4;   // As: 16 rows x 16 f4 cols
    const int bcol = (lc4 < 32) ? (h*32 + lc4) : (384 + h*32 + lc4 - 32);

    #define AV_LOAD(KC) { \
        _Pragma("unroll") for (int s = 0; s < 2; s++) { \
            int r = alr + s*16; \
            ra[s] = *(const float4*)&g_att[((size_t)h*L + m0 + r)*L + (KC)*64 + lc4]; } \
        _Pragma("unroll") for (int s = 0; s < 4; s++) { \
            int r = alr + s*16; \
            rb[s] = *(const float4*)&g_avin[((KC)*64 + r)*AVD + bcol]; } }
    #define AV_STORE() { \
        _Pragma("unroll") for (int s = 0; s < 2; s++) { \
            int r = alr + s*16; \
            *(float4*)&As[r][lc4] = make_float4(tf32f(ra[s].x), tf32f(ra[s].y), tf32f(ra[s].z), tf32f(ra[s].w)); } \
        _Pragma("unroll") for (int s = 0; s < 4; s++) { \
            int r = alr + s*16; \
            *(float4*)&Bs[r][lc4] = make_float4(tf32f(rb[s].x), tf32f(rb[s].y), tf32f(rb[s].z), tf32f(rb[s].w)); } }

    AV_LOAD(0);
    for (int kc = 0; kc < 8; kc++) {
        AV_STORE();
        __syncthreads();
        if (kc < 7) AV_LOAD(kc+1);
        const int ar = wm*16 + (lane >> 2);
        const int ac = lane & 3;
        #pragma unroll
        for (int ks = 0; ks < 8; ks++) {
            unsigned a0 = FB(As[ar][ks*8 + ac]);
            unsigned a1 = FB(As[ar+8][ks*8 + ac]);
            unsigned a2 = FB(As[ar][ks*8 + ac + 4]);
            unsigned a3 = FB(As[ar+8][ks*8 + ac + 4]);
            #pragma unroll
            for (int ns = 0; ns < 2; ns++) {
                int bn = wn*16 + ns*8 + (lane >> 2);
                unsigned b0 = FB(Bs[ks*8 + (lane & 3)][bn]);
                unsigned b1 = FB(Bs[ks*8 + (lane & 3) + 4][bn]);
                mma_tf32(acc[ns][0], acc[ns][1], acc[ns][2], acc[ns][3],
                         a0, a1, a2, a3, b0, b1);
            }
        }
        __syncthreads();
    }
    #undef AV_LOAD
    #undef AV_STORE
    {
        int r0 = m0 + wm*16 + (lane >> 2);
        int r1 = r0 + 8;
        #pragma unroll
        for (int ns = 0; ns < 2; ns++) {
            int col = wn*16 + ns*8 + (lane & 3)*2;
            if (col < 32) {
                g_comb[(size_t)r0*COMBD + h*32 + col]     = acc[ns][0];
                g_comb[(size_t)r0*COMBD + h*32 + col + 1] = acc[ns][1];
                g_comb[(size_t)r1*COMBD + h*32 + col]     = acc[ns][2];
                g_comb[(size_t)r1*COMBD + h*32 + col + 1] = acc[ns][3];
            } else {
                int c2 = col - 32;
                g_ptsraw[r0*384 + h*32 + c2]     = acc[ns][0];
                g_ptsraw[r0*384 + h*32 + c2 + 1] = acc[ns][1];
                g_ptsraw[r1*384 + h*32 + c2]     = acc[ns][2];
                g_ptsraw[r1*384 + h*32 + c2 + 1] = acc[ns][3];
            }
        }
    }
}

// ---------------- K7: point frame transform + norm ----------------
__global__ void k_pts(const float* __restrict__ rot, const float* __restrict__ trans) {
    int idx = blockIdx.x*256 + threadIdx.x;
    if (idx >= L*96) return;
    int i = idx / 96, u = idx % 96;
    int h = u >> 3, p = u & 7;
    const float* src = &g_ptsraw[i*384 + h*32 + p*3];
    float T0 = trans[i*3+0], T1 = trans[i*3+1], T2 = trans[i*3+2];
    float px = src[0]-T0, py = src[1]-T1, pz = src[2]-T2;
    const float* R = &rot[i*9];
    float lx = R[0]*px + R[3]*py + R[6]*pz;
    float ly = R[1]*px + R[4]*py + R[7]*pz;
    float lz = R[2]*px + R[5]*py + R[8]*pz;
    float nrm = sqrtf(lx*lx + ly*ly + lz*lz);
    float* dst = &g_comb[(size_t)i*COMBD + 384 + u*4];
    dst[0] = nrm; dst[1] = lx; dst[2] = ly; dst[3] = lz;
}

// ---------------- K8: combined @ Wo, split-K=6 (tf32, pipelined) ----------------
__global__ void k_final4(const float* __restrict__ Wo) {
    const int kc4 = blockIdx.z;                 // 0..5
    const int n0 = blockIdx.x*64, m0 = blockIdx.y*64;
    const int t = threadIdx.x;  // 256
    const int warp = t >> 5, lane = t & 31;
    __shared__ float As[64][68];
    __shared__ float Bs[64][68];

    const int wm = warp & 3;
    const int wn = warp >> 2;
    float acc[4][4] = {};
    float4 ra[4], rb[4];

    const int lr = t >> 4, lc4 = (t & 15) * 4;
    const int kbeg = kc4*384;

    #define F4_LOAD(KC) { int k0 = kbeg + (KC)*64; _Pragma("unroll") for (int s = 0; s < 4; s++) { \
        int r = lr + s*16; \
        ra[s] = *(const float4*)&g_comb[(size_t)(m0 + r)*COMBD + k0 + lc4]; \
        rb[s] = *(const float4*)&Wo[(size_t)(k0 + r)*DS + n0 + lc4]; } }
    #define F4_STORE() { _Pragma("unroll") for (int s = 0; s < 4; s++) { \
        int r = lr + s*16; \
        *(float4*)&As[r][lc4] = make_float4(tf32f(ra[s].x), tf32f(ra[s].y), tf32f(ra[s].z), tf32f(ra[s].w)); \
        *(float4*)&Bs[r][lc4] = make_float4(tf32f(rb[s].x), tf32f(rb[s].y), tf32f(rb[s].z), tf32f(rb[s].w)); } }

    F4_LOAD(0);
    for (int kc = 0; kc < 6; kc++) {
        F4_STORE();
        __syncthreads();
        if (kc < 5) F4_LOAD(kc+1);
        const int ar = wm*16 + (lane >> 2);
        const int ac = lane & 3;
        #pragma unroll
        for (int ks = 0; ks < 8; ks++) {
            unsigned a0 = FB(As[ar][ks*8 + ac]);
            unsigned a1 = FB(As[ar+8][ks*8 + ac]);
            unsigned a2 = FB(As[ar][ks*8 + ac + 4]);
            unsigned a3 = FB(As[ar+8][ks*8 + ac + 4]);
            #pragma unroll
            for (int ns = 0; ns < 4; ns++) {
                int bn = wn*32 + ns*8 + (lane >> 2);
                unsigned b0 = FB(Bs[ks*8 + (lane & 3)][bn]);
                unsigned b1 = FB(Bs[ks*8 + (lane & 3) + 4][bn]);
                mma_tf32(acc[ns][0], acc[ns][1], acc[ns][2], acc[ns][3],
                         a0, a1, a2, a3, b0, b1);
            }
        }
        __syncthreads();
    }
    #undef F4_LOAD
    #undef F4_STORE
    {
        int r0 = m0 + wm*16 + (lane >> 2);
        int r1 = r0 + 8;
        #pragma unroll
        for (int ns = 0; ns < 4; ns++) {
            int col = n0 + wn*32 + ns*8 + (lane & 3)*2;
            g_fpart[((size_t)kc4*L + r0)*DS + col]     = acc[ns][0];
            g_fpart[((size_t)kc4*L + r0)*DS + col + 1] = acc[ns][1];
            g_fpart[((size_t)kc4*L + r1)*DS + col]     = acc[ns][2];
            g_fpart[((size_t)kc4*L + r1)*DS + col + 1] = acc[ns][3];
        }
    }
}

__global__ void k_fred(const float* __restrict__ bo, float* __restrict__ out) {
    int f = blockIdx.x*256 + threadIdx.x;
    int n = (f*4) % DS;
    float4 p0 = *(const float4*)&g_fpart[(size_t)0*L*DS + f*4];
    float4 p1 = *(const float4*)&g_fpart[(size_t)1*L*DS + f*4];
    float4 p2 = *(const float4*)&g_fpart[(size_t)2*L*DS + f*4];
    float4 p3 = *(const float4*)&g_fpart[(size_t)3*L*DS + f*4];
    float4 p4 = *(const float4*)&g_fpart[(size_t)4*L*DS + f*4];
    float4 p5 = *(const float4*)&g_fpart[(size_t)5*L*DS + f*4];
    float4 bb = *(const float4*)&bo[n];
    float4 o = make_float4(p0.x+p1.x+p2.x+p3.x+p4.x+p5.x+bb.x,
                           p0.y+p1.y+p2.y+p3.y+p4.y+p5.y+bb.y,
                           p0.z+p1.z+p2.z+p3.z+p4.z+p5.z+bb.z,
                           p0.w+p1.w+p2.w+p3.w+p4.w+p5.w+bb.w);
    *(float4*)&out[f*4] = o;
}

// ---------------- launch ----------------
extern "C" void kernel_launch(void* const* d_in, const int* in_sizes, int n_in,
                              void* d_out, int out_size) {
    const float* single_ = (const float*)d_in[0];
    const float* pair    = (const float*)d_in[1];
    const float* rot     = (const float*)d_in[2];
    const float* trans   = (const float*)d_in[3];
    const float* mask    = (const float*)d_in[4];
    const float* ln_w    = (const float*)d_in[5];
    const float* ln_b    = (const float*)d_in[6];
    const float* Wq      = (const float*)d_in[7];
    const float* bq      = (const float*)d_in[8];
    const float* Wk      = (const float*)d_in[9];
    const float* bk      = (const float*)d_in[10];
    const float* Wv      = (const float*)d_in[11];
    const float* bv      = (const float*)d_in[12];
    const float* Wqp     = (const float*)d_in[13];
    const float* bqp     = (const float*)d_in[14];
    const float* Wkp     = (const float*)d_in[15];
    const float* bkp     = (const float*)d_in[16];
    const float* Wvp     = (const float*)d_in[17];
    const float* bvp     = (const float*)d_in[18];
    const float* Wpb     = (const float*)d_in[19];
    const float* bpb     = (const float*)d_in[20];
    const float* Wo      = (const float*)d_in[21];
    const float* bo      = (const float*)d_in[22];
    const float* w_c     = (const float*)d_in[23];
    const float* w_l     = (const float*)d_in[24];
    const float* gamma_h = (const float*)d_in[25];

    k_ln<<<L, 384>>>(single_, ln_w, ln_b);
    k_projgemm<<<dim3(PROJD/64, L/64), 256>>>(Wq, bq, Wk, bk, Wv, bv,
                                              Wqp, bqp, Wkp, bkp, Wvp, bvp);
    k_rot<<<L, 384>>>(rot, trans, w_c, w_l, gamma_h);
    k_logits<<<dim3(L/64, L/64, H_), 256>>>();

    const int dyn = 18968 * (int)sizeof(float);  // 75872
    cudaFuncSetAttribute(k_fused, cudaFuncAttributeMaxDynamicSharedMemorySize, dyn);
    k_fused<<<L, 256, dyn>>>(pair, Wpb, bpb, mask);

    k_av<<<dim3(H_, L/32), 256>>>();
    k_pts<<<(L*96 + 255)/256, 256>>>(rot, trans);
    k_final4<<<dim3(DS/64, L/64, 6), 256>>>(Wo);
    k_fred<<<192, 256>>>(bo, (float*)d_out);
}